// round 10
// baseline (speedup 1.0000x reference)
#include <cuda_runtime.h>
#include <cstdint>

// ============================================================================
// Conformer layer, fp32 SIMT implementation.
// B=2, N=2048, CACHE=512, KV=2560, D_MODEL=768, H=12, HD=64, FF=3072, KSZ=31
// ============================================================================

#define B_    2
#define N_    2048
#define CACHE_ 512
#define KV_   2560
#define DM_   768
#define NH_   12
#define HD_   64
#define FF_   3072
#define ROWS_ (B_*N_)          // 4096
#define EPSF  1e-5f

// ---------------- scratch (device globals; no allocation allowed) -----------
__device__ float g_y   [ROWS_*DM_];
__device__ float g_h   [ROWS_*FF_];
__device__ float g_x1  [ROWS_*DM_];
__device__ float g_x2  [ROWS_*DM_];
__device__ float g_attn[ROWS_*DM_];
__device__ float g_glu [ROWS_*DM_];
__device__ float g_conv[ROWS_*DM_];
__device__ float g_xc  [ROWS_*DM_];
__device__ float g_x3  [ROWS_*DM_];
__device__ float g_kv  [(size_t)B_*KV_*2*NH_*HD_];   // kv fallback scratch
__device__ float g_qrot[(size_t)B_*NH_*N_*HD_];
__device__ float g_krot[(size_t)B_*NH_*KV_*HD_];
__device__ float g_v   [(size_t)B_*NH_*KV_*HD_];
__device__ float g_stats[2*DM_];

// ---------------- FMA-only transcendentals (keep MUFU idle) -----------------
__device__ __forceinline__ float fexp(float x) {
    x = fmaxf(x, -87.0f);                       // handles -inf / mask values
    float z = x * 1.44269504088896340f;         // log2(e)
    float r = z + 12582912.0f;                  // round-to-nearest int trick
    int   n = __float_as_int(r) - 0x4B400000;
    float f = z - (r - 12582912.0f);            // f in [-0.5, 0.5]
    float p = 1.5403530393e-4f;
    p = fmaf(p, f, 1.3333558146e-3f);
    p = fmaf(p, f, 9.6181291076e-3f);
    p = fmaf(p, f, 5.5504108664e-2f);
    p = fmaf(p, f, 2.4022650696e-1f);
    p = fmaf(p, f, 6.9314718056e-1f);
    p = fmaf(p, f, 1.0f);
    return __int_as_float((n + 127) << 23) * p;
}

__device__ __forceinline__ float fsig(float z) {
    float e = fexp(-fabsf(z));                  // (0, 1]
    float d = 1.0f + e;                         // d in [1, 2]
    // FIX (round 9): Newton-reciprocal seed valid on [1,2]. The previous
    // seed (48/17 - 32/17*d) targets [0.5,1]; it is NEGATIVE at d=2 and
    // Newton diverges -> sigmoid(0) ~ -2381, destroying every GELU/GLU/swish
    // and fully decorrelating the output (rel_err = sqrt(2)).
    float r = fmaf(-0.457107f, d, 1.457107f);   // |1 - d*r| <= 0.086 on [1,2]
    r = r * fmaf(-d, r, 2.0f);
    r = r * fmaf(-d, r, 2.0f);
    r = r * fmaf(-d, r, 2.0f);                  // rel err ~3e-9
    return (z >= 0.0f) ? r : e * r;
}

__device__ __forceinline__ float fgelu(float x) {
    // jax approximate gelu: 0.5x(1+tanh(u)) == x*sigmoid(2u)
    float u = 1.5957691216057308f * fmaf(0.044715f * x, x * x, x);
    return x * fsig(u);
}

// ---------------- rmsnorm over rows of width 768 ----------------------------
__global__ __launch_bounds__(256) void rmsnorm_kernel(
    const float* __restrict__ x, const float* __restrict__ w,
    float* __restrict__ out)
{
    int row = blockIdx.x;
    const float* xr = x + (size_t)row * DM_;
    float v[3]; float s = 0.f;
#pragma unroll
    for (int i = 0; i < 3; i++) {
        v[i] = xr[threadIdx.x + i * 256];
        s = fmaf(v[i], v[i], s);
    }
#pragma unroll
    for (int off = 16; off; off >>= 1) s += __shfl_xor_sync(~0u, s, off);
    __shared__ float red[8];
    if ((threadIdx.x & 31) == 0) red[threadIdx.x >> 5] = s;
    __syncthreads();
    float tot = 0.f;
#pragma unroll
    for (int i = 0; i < 8; i++) tot += red[i];
    float scale = rsqrtf(tot * (1.0f / DM_) + EPSF);
    float* orow = out + (size_t)row * DM_;
#pragma unroll
    for (int i = 0; i < 3; i++) {
        int c = threadIdx.x + i * 256;
        orow[c] = v[i] * scale * w[c];
    }
}

// ---------------- SGEMM 128x128x8, 8x8 microtile, fused epilogues -----------
enum { EPI_NONE = 0, EPI_BIAS, EPI_GELU, EPI_HALF_RES, EPI_RES };

template <int EPI>
__global__ __launch_bounds__(256, 2) void sgemm_k(
    const float* __restrict__ A, const float* __restrict__ Bw,
    const float* __restrict__ bias, const float* __restrict__ res,
    float* __restrict__ C, int M, int N, int K)
{
    __shared__ float As[8][128];
    __shared__ float Bs[8][128];
    int tid = threadIdx.x;
    int cRow = blockIdx.y * 128, cCol = blockIdx.x * 128;
    const float* Ag = A + (size_t)cRow * K;
    const float* Bg = Bw + cCol;
    int aRow = tid >> 1,  aCol = (tid & 1) * 4;
    int bRow = tid >> 5,  bCol = (tid & 31) * 4;
    int tr = (tid >> 4) * 8, tc = (tid & 15) * 8;
    float acc[8][8] = {};
    for (int k0 = 0; k0 < K; k0 += 8) {
        float4 a4 = *(const float4*)(Ag + (size_t)aRow * K + k0 + aCol);
        As[aCol + 0][aRow] = a4.x; As[aCol + 1][aRow] = a4.y;
        As[aCol + 2][aRow] = a4.z; As[aCol + 3][aRow] = a4.w;
        *(float4*)&Bs[bRow][bCol] =
            *(const float4*)(Bg + (size_t)(k0 + bRow) * N + bCol);
        __syncthreads();
#pragma unroll
        for (int k = 0; k < 8; k++) {
            float ra[8], rb[8];
            *(float4*)(ra)     = *(float4*)&As[k][tr];
            *(float4*)(ra + 4) = *(float4*)&As[k][tr + 4];
            *(float4*)(rb)     = *(float4*)&Bs[k][tc];
            *(float4*)(rb + 4) = *(float4*)&Bs[k][tc + 4];
#pragma unroll
            for (int i = 0; i < 8; i++)
#pragma unroll
                for (int j = 0; j < 8; j++)
                    acc[i][j] = fmaf(ra[i], rb[j], acc[i][j]);
        }
        __syncthreads();
    }
#pragma unroll
    for (int i = 0; i < 8; i++) {
        size_t r = (size_t)(cRow + tr + i);
#pragma unroll
        for (int j = 0; j < 8; j += 4) {
            int c = cCol + tc + j;
            float o[4];
#pragma unroll
            for (int q = 0; q < 4; q++) {
                float v = acc[i][j + q];
                if (EPI == EPI_BIAS)      v = v + bias[c + q];
                if (EPI == EPI_GELU)      v = fgelu(v + bias[c + q]);
                if (EPI == EPI_HALF_RES)  v = fmaf(0.5f, v + bias[c + q],
                                                   res[r * N + c + q]);
                if (EPI == EPI_RES)       v = v + res[r * N + c + q];
                o[q] = v;
            }
            *(float4*)&C[r * N + c] = *(float4*)o;
        }
    }
}

// ---------------- qkv post: per-head rmsnorm + rope + scatter ---------------
__global__ __launch_bounds__(384) void qkvpost_kernel(
    const float* __restrict__ qkv, const float* __restrict__ qw,
    const float* __restrict__ kw, float* __restrict__ kvout,
    float* __restrict__ qrot, float* __restrict__ krot,
    float* __restrict__ vout)
{
    int row = blockIdx.x;
    int b = row >> 11, n = row & 2047;
    int h = threadIdx.x >> 5, l = threadIdx.x & 31;
    const float* base = qkv + (size_t)row * (3 * NH_ * HD_) + h * (HD_ * 3);
    float q0 = base[l * 3 + 0],        k0 = base[l * 3 + 1],        v0 = base[l * 3 + 2];
    float q1 = base[(l + 32) * 3 + 0], k1 = base[(l + 32) * 3 + 1], v1 = base[(l + 32) * 3 + 2];
    float sq = fmaf(q0, q0, q1 * q1), sk = fmaf(k0, k0, k1 * k1);
#pragma unroll
    for (int off = 16; off; off >>= 1) {
        sq += __shfl_xor_sync(~0u, sq, off);
        sk += __shfl_xor_sync(~0u, sk, off);
    }
    float rq = rsqrtf(sq * (1.0f / HD_) + EPSF);
    float rk = rsqrtf(sk * (1.0f / HD_) + EPSF);
    q0 *= rq * qw[l];  q1 *= rq * qw[l + 32];
    k0 *= rk * kw[l];  k1 *= rk * kw[l + 32];

    int t = CACHE_ + n;
    size_t kvo = ((((size_t)b * KV_ + t) * 2 + 0) * NH_ + h) * HD_;
    kvout[kvo + l] = k0;  kvout[kvo + l + 32] = k1;
    kvout[kvo + NH_ * HD_ + l] = v0;  kvout[kvo + NH_ * HD_ + l + 32] = v1;

    float inv = expf(-(float)l * (9.210340371976184f / 32.0f)); // 10000^{-l/32}
    float ang = (float)t * inv;
    float sn, cs; sincosf(ang, &sn, &cs);
    size_t qidx = (((size_t)(b * NH_ + h)) * N_ + n) * HD_;
    qrot[qidx + l]      = (q0 * cs - q1 * sn) * 0.125f;  // fold 1/sqrt(64)
    qrot[qidx + l + 32] = (q1 * cs + q0 * sn) * 0.125f;
    size_t kidx = (((size_t)(b * NH_ + h)) * KV_ + t) * HD_;
    krot[kidx + l]      = k0 * cs - k1 * sn;
    krot[kidx + l + 32] = k1 * cs + k0 * sn;
    vout[kidx + l] = v0;  vout[kidx + l + 32] = v1;
}

// ---------------- cache prep: copy cache to output, rope cached K -----------
__global__ __launch_bounds__(384) void cacheprep_kernel(
    const float* __restrict__ cached, float* __restrict__ kvout,
    float* __restrict__ krot, float* __restrict__ vout)
{
    int row = blockIdx.x;
    int b = row >> 9, t = row & 511;
    int h = threadIdx.x >> 5, l = threadIdx.x & 31;
    size_t ci = ((((size_t)b * CACHE_ + t) * 2 + 0) * NH_ + h) * HD_;
    float k0 = cached[ci + l],        k1 = cached[ci + l + 32];
    float v0 = cached[ci + NH_ * HD_ + l], v1 = cached[ci + NH_ * HD_ + l + 32];
    size_t kvo = ((((size_t)b * KV_ + t) * 2 + 0) * NH_ + h) * HD_;
    kvout[kvo + l] = k0;  kvout[kvo + l + 32] = k1;
    kvout[kvo + NH_ * HD_ + l] = v0;  kvout[kvo + NH_ * HD_ + l + 32] = v1;
    float inv = expf(-(float)l * (9.210340371976184f / 32.0f));
    float ang = (float)t * inv;
    float sn, cs; sincosf(ang, &sn, &cs);
    size_t kidx = (((size_t)(b * NH_ + h)) * KV_ + t) * HD_;
    krot[kidx + l]      = k0 * cs - k1 * sn;
    krot[kidx + l + 32] = k1 * cs + k0 * sn;
    vout[kidx + l] = v0;  vout[kidx + l + 32] = v1;
}

// ---------------- flash attention: 64q x 64kv tiles, fp32, poly-exp ---------
__global__ __launch_bounds__(256) void flash_kernel(
    const float* __restrict__ Q, const float* __restrict__ Kr,
    const float* __restrict__ V, float* __restrict__ O)
{
    extern __shared__ float sm[];
    float* Qst = sm;                 // [64 d][64 q]  (transposed)
    float* Kst = sm + 4096;          // [64 d][64 k]  (transposed)
    float* Vs  = sm + 8192;          // [64 k][64 d]
    float* Ssm = sm + 12288;         // [64 q][68]
    __shared__ float m_s[64], l_s[64], c_s[64];

    int tid = threadIdx.x;
    int qt = blockIdx.x, h = blockIdx.y, b = blockIdx.z;
    const float* qbase = Q + (((size_t)(b * NH_ + h)) * N_ + qt * 64) * HD_;
    const float* kbase = Kr + ((size_t)(b * NH_ + h)) * KV_ * HD_;
    const float* vbase = V  + ((size_t)(b * NH_ + h)) * KV_ * HD_;

#pragma unroll
    for (int it = 0; it < 4; it++) {
        int e = tid + it * 256;
        int q = e >> 4, d4 = (e & 15) * 4;
        float4 a = *(const float4*)(qbase + q * 64 + d4);
        Qst[(d4 + 0) * 64 + q] = a.x; Qst[(d4 + 1) * 64 + q] = a.y;
        Qst[(d4 + 2) * 64 + q] = a.z; Qst[(d4 + 3) * 64 + q] = a.w;
    }
    if (tid < 64) { m_s[tid] = -1e30f; l_s[tid] = 0.f; }
    int ty = tid >> 4, tx = tid & 15;
    float o[4][4] = {};

    for (int kc = 0; kc < KV_ / 64; kc++) {
        const float* kb = kbase + (size_t)kc * 64 * 64;
        const float* vb = vbase + (size_t)kc * 64 * 64;
        __syncthreads();
#pragma unroll
        for (int it = 0; it < 4; it++) {
            int e = tid + it * 256;
            int r = e >> 4, d4 = (e & 15) * 4;
            float4 a = *(const float4*)(kb + r * 64 + d4);
            Kst[(d4 + 0) * 64 + r] = a.x; Kst[(d4 + 1) * 64 + r] = a.y;
            Kst[(d4 + 2) * 64 + r] = a.z; Kst[(d4 + 3) * 64 + r] = a.w;
            *(float4*)&Vs[r * 64 + d4] = *(const float4*)(vb + r * 64 + d4);
        }
        __syncthreads();
        float s[4][4] = {};
#pragma unroll 16
        for (int d = 0; d < 64; d++) {
            float4 qa = *(float4*)&Qst[d * 64 + ty * 4];
            float4 ka = *(float4*)&Kst[d * 64 + tx * 4];
            float ra[4] = {qa.x, qa.y, qa.z, qa.w};
            float rb[4] = {ka.x, ka.y, ka.z, ka.w};
#pragma unroll
            for (int i = 0; i < 4; i++)
#pragma unroll
                for (int j = 0; j < 4; j++)
                    s[i][j] = fmaf(ra[i], rb[j], s[i][j]);
        }
#pragma unroll
        for (int i = 0; i < 4; i++)
            *(float4*)&Ssm[(ty * 4 + i) * 68 + tx * 4] = *(float4*)s[i];
        __syncthreads();
        if (tid < 64) {
            float mo = m_s[tid], mx = mo;
            const float* srow = &Ssm[tid * 68];
#pragma unroll 16
            for (int kk = 0; kk < 64; kk++) mx = fmaxf(mx, srow[kk]);
            float corr = fexp(mo - mx);
            float l = l_s[tid] * corr;
            float* prow = &Ssm[tid * 68];
#pragma unroll 8
            for (int kk = 0; kk < 64; kk++) {
                float p = fexp(prow[kk] - mx);
                prow[kk] = p;
                l += p;
            }
            m_s[tid] = mx; l_s[tid] = l; c_s[tid] = corr;
        }
        __syncthreads();
#pragma unroll
        for (int i = 0; i < 4; i++) {
            float cc = c_s[ty * 4 + i];
#pragma unroll
            for (int j = 0; j < 4; j++) o[i][j] *= cc;
        }
#pragma unroll 8
        for (int kk = 0; kk < 64; kk++) {
            float4 vv = *(float4*)&Vs[kk * 64 + tx * 4];
            float rv[4] = {vv.x, vv.y, vv.z, vv.w};
#pragma unroll
            for (int i = 0; i < 4; i++) {
                float p = Ssm[(ty * 4 + i) * 68 + kk];
#pragma unroll
                for (int j = 0; j < 4; j++)
                    o[i][j] = fmaf(p, rv[j], o[i][j]);
            }
        }
    }
    __syncthreads();
#pragma unroll
    for (int i = 0; i < 4; i++) {
        int q = ty * 4 + i;
        float invl = 1.0f / l_s[q];
        size_t row = (size_t)b * N_ + qt * 64 + q;
        float r4[4];
#pragma unroll
        for (int j = 0; j < 4; j++) r4[j] = o[i][j] * invl;
        *(float4*)&O[row * DM_ + h * HD_ + tx * 4] = *(float4*)r4;
    }
}

// ---------------- conv module pieces ----------------------------------------
__global__ __launch_bounds__(256) void glu_kernel(
    const float* __restrict__ in, float* __restrict__ out)
{
    int idx = blockIdx.x * 256 + threadIdx.x;
    int r = idx / DM_, c = idx - r * DM_;
    float a  = in[(size_t)r * (2 * DM_) + c];
    float bb = in[(size_t)r * (2 * DM_) + DM_ + c];
    out[idx] = a * fsig(bb);
}

__global__ void zero_stats_kernel(float* __restrict__ st) {
    st[blockIdx.x * 256 + threadIdx.x] = 0.f;
}

__global__ __launch_bounds__(768) void dwconv_kernel(
    const float* __restrict__ in, const float* __restrict__ w,
    const float* __restrict__ bias, float* __restrict__ out)
{
    int row = blockIdx.x;
    int b = row >> 11, t = row & 2047;
    int c = threadIdx.x;
    const float* basep = in + ((size_t)b * N_) * DM_ + c;
    const float* wp = w + c * 31;
    float acc = bias[c];
#pragma unroll
    for (int k = 0; k < 31; k++) {
        int tt = t + k - 15;
        if (tt >= 0 && tt < N_)
            acc = fmaf(basep[(size_t)tt * DM_], wp[k], acc);
    }
    out[(size_t)row * DM_ + c] = acc;
}

__global__ __launch_bounds__(256) void stats_kernel(
    const float* __restrict__ x, float* __restrict__ st)
{
    int blk = blockIdx.x, tid = threadIdx.x;
    float s[3] = {}, ss[3] = {};
    for (int r = 0; r < 64; r++) {
        size_t row = (size_t)blk * 64 + r;
#pragma unroll
        for (int i = 0; i < 3; i++) {
            float v = x[row * DM_ + tid + i * 256];
            s[i] += v;
            ss[i] = fmaf(v, v, ss[i]);
        }
    }
#pragma unroll
    for (int i = 0; i < 3; i++) {
        atomicAdd(&st[tid + i * 256], s[i]);
        atomicAdd(&st[DM_ + tid + i * 256], ss[i]);
    }
}

__global__ __launch_bounds__(256) void bnswish_kernel(
    float* __restrict__ x, const float* __restrict__ st,
    const float* __restrict__ g, const float* __restrict__ bt)
{
    int idx = blockIdx.x * 256 + threadIdx.x;
    int c = idx % DM_;
    float m   = st[c] * (1.0f / ROWS_);
    float var = st[DM_ + c] * (1.0f / ROWS_) - m * m;
    float y = (x[idx] - m) * rsqrtf(var + EPSF) * g[c] + bt[c];
    x[idx] = y * fsig(y);
}

// ---------------- host ------------------------------------------------------
static float* symaddr(const void* s) {
    void* p = nullptr;
    cudaGetSymbolAddress(&p, s);
    return (float*)p;
}

extern "C" void kernel_launch(void* const* d_in, const int* in_sizes, int n_in,
                              void* d_out, int out_size)
{
    const float* x = (const float*)d_in[0];
    int ic = 4;
    for (int i = 1; i < n_in; i++)
        if (in_sizes[i] == B_ * KV_ * 2 * NH_ * HD_) { ic = i; break; }
    const float* cached  = (const float*)d_in[ic];
    const float* ff1_nw  = (const float*)d_in[ic + 1];
    const float* ff1_w1  = (const float*)d_in[ic + 2];
    const float* ff1_b1  = (const float*)d_in[ic + 3];
    const float* ff1_w2  = (const float*)d_in[ic + 4];
    const float* ff1_b2  = (const float*)d_in[ic + 5];
    const float* attn_nw = (const float*)d_in[ic + 6];
    const float* qkv_w   = (const float*)d_in[ic + 7];
    const float* out_w   = (const float*)d_in[ic + 8];
    const float* q_nw    = (const float*)d_in[ic + 9];
    const float* k_nw    = (const float*)d_in[ic + 10];
    const float* conv_nw = (const float*)d_in[ic + 11];
    const float* pw1_w   = (const float*)d_in[ic + 12];
    const float* pw1_b   = (const float*)d_in[ic + 13];
    const float* dw_w    = (const float*)d_in[ic + 14];
    const float* dw_b    = (const float*)d_in[ic + 15];
    const float* bn_g    = (const float*)d_in[ic + 16];
    const float* bn_b    = (const float*)d_in[ic + 17];
    const float* pw2_w   = (const float*)d_in[ic + 18];
    const float* pw2_b   = (const float*)d_in[ic + 19];
    const float* ff2_nw  = (const float*)d_in[ic + 20];
    const float* ff2_w1  = (const float*)d_in[ic + 21];
    const float* ff2_b1  = (const float*)d_in[ic + 22];
    const float* ff2_w2  = (const float*)d_in[ic + 23];
    const float* ff2_b2  = (const float*)d_in[ic + 24];
    const float* out_nw  = (const float*)d_in[ic + 25];

    float* outx = (float*)d_out;
    bool write_kv = (out_size >= ROWS_ * DM_ + B_ * KV_ * 2 * NH_ * HD_);
    float* kvdst = write_kv ? (outx + (size_t)ROWS_ * DM_) : symaddr(g_kv);

    float* p_y    = symaddr(g_y);
    float* p_h    = symaddr(g_h);
    float* p_x1   = symaddr(g_x1);
    float* p_x2   = symaddr(g_x2);
    float* p_attn = symaddr(g_attn);
    float* p_glu  = symaddr(g_glu);
    float* p_conv = symaddr(g_conv);
    float* p_xc   = symaddr(g_xc);
    float* p_x3   = symaddr(g_x3);
    float* p_qr   = symaddr(g_qrot);
    float* p_kr   = symaddr(g_krot);
    float* p_v    = symaddr(g_v);
    float* p_st   = symaddr(g_stats);

    const int FLASH_SMEM = (4096 * 3 + 64 * 68) * 4;   // 66560
    cudaFuncSetAttribute(flash_kernel,
                         cudaFuncAttributeMaxDynamicSharedMemorySize, FLASH_SMEM);

    // ---- FF1: x1 = 0.5*(gelu(rms(x)W1+b1)W2 + b2) + x
    rmsnorm_kernel<<<ROWS_, 256>>>(x, ff1_nw, p_y);
    sgemm_k<EPI_GELU><<<dim3(FF_ / 128, ROWS_ / 128), 256>>>(
        p_y, ff1_w1, ff1_b1, nullptr, p_h, ROWS_, FF_, DM_);
    sgemm_k<EPI_HALF_RES><<<dim3(DM_ / 128, ROWS_ / 128), 256>>>(
        p_h, ff1_w2, ff1_b2, x, p_x1, ROWS_, DM_, FF_);

    // ---- Attention
    rmsnorm_kernel<<<ROWS_, 256>>>(p_x1, attn_nw, p_y);
    sgemm_k<EPI_NONE><<<dim3((3 * NH_ * HD_) / 128, ROWS_ / 128), 256>>>(
        p_y, qkv_w, nullptr, nullptr, p_h, ROWS_, 3 * NH_ * HD_, DM_);
    cacheprep_kernel<<<B_ * CACHE_, 384>>>(cached, kvdst, p_kr, p_v);
    qkvpost_kernel<<<ROWS_, 384>>>(p_h, q_nw, k_nw, kvdst, p_qr, p_kr, p_v);
    flash_kernel<<<dim3(N_ / 64, NH_, B_), 256, FLASH_SMEM>>>(p_qr, p_kr, p_v, p_attn);
    sgemm_k<EPI_RES><<<dim3(DM_ / 128, ROWS_ / 128), 256>>>(
        p_attn, out_w, nullptr, p_x1, p_x2, ROWS_, DM_, DM_);

    // ---- Conv module (no residual)
    rmsnorm_kernel<<<ROWS_, 256>>>(p_x2, conv_nw, p_y);
    sgemm_k<EPI_BIAS><<<dim3((2 * DM_) / 128, ROWS_ / 128), 256>>>(
        p_y, pw1_w, pw1_b, nullptr, p_h, ROWS_, 2 * DM_, DM_);
    glu_kernel<<<(ROWS_ * DM_) / 256, 256>>>(p_h, p_glu);
    zero_stats_kernel<<<(2 * DM_) / 256, 256>>>(p_st);
    dwconv_kernel<<<ROWS_, DM_>>>(p_glu, dw_w, dw_b, p_conv);
    stats_kernel<<<64, 256>>>(p_conv, p_st);
    bnswish_kernel<<<(ROWS_ * DM_) / 256, 256>>>(p_conv, p_st, bn_g, bn_b);
    sgemm_k<EPI_BIAS><<<dim3(DM_ / 128, ROWS_ / 128), 256>>>(
        p_conv, pw2_w, pw2_b, nullptr, p_xc, ROWS_, DM_, DM_);

    // ---- FF2: x3 = 0.5*(gelu(rms(xc)W1+b1)W2 + b2) + xc
    rmsnorm_kernel<<<ROWS_, 256>>>(p_xc, ff2_nw, p_y);
    sgemm_k<EPI_GELU><<<dim3(FF_ / 128, ROWS_ / 128), 256>>>(
        p_y, ff2_w1, ff2_b1, nullptr, p_h, ROWS_, FF_, DM_);
    sgemm_k<EPI_HALF_RES><<<dim3(DM_ / 128, ROWS_ / 128), 256>>>(
        p_h, ff2_w2, ff2_b2, p_xc, p_x3, ROWS_, DM_, FF_);

    // ---- final rmsnorm -> output x
    rmsnorm_kernel<<<ROWS_, 256>>>(p_x3, out_nw, outx);
}

// round 17
// speedup vs baseline: 2.8784x; 2.8784x over previous
#include <cuda_runtime.h>
#include <cuda_bf16.h>
#include <cstdint>

// ============================================================================
// Conformer layer. GEMMs via mma.sync bf16 (3-term split, HMMA tensor cores),
// rest fp32 SIMT.  NOTE: harness ptxas targets baseline sm_103 -> no tcgen05.
// B=2, N=2048, CACHE=512, KV=2560, D_MODEL=768, H=12, HD=64, FF=3072, KSZ=31
// ============================================================================

#define B_    2
#define N_    2048
#define CACHE_ 512
#define KV_   2560
#define DM_   768
#define NH_   12
#define HD_   64
#define FF_   3072
#define ROWS_ (B_*N_)          // 4096
#define EPSF  1e-5f

// ---------------- scratch (device globals; no allocation allowed) -----------
__device__ float g_y   [ROWS_*DM_];
__device__ float g_h   [ROWS_*FF_];
__device__ float g_x1  [ROWS_*DM_];
__device__ float g_x2  [ROWS_*DM_];
__device__ float g_attn[ROWS_*DM_];
__device__ float g_glu [ROWS_*DM_];
__device__ float g_conv[ROWS_*DM_];
__device__ float g_xc  [ROWS_*DM_];
__device__ float g_x3  [ROWS_*DM_];
__device__ float g_kv  [(size_t)B_*KV_*2*NH_*HD_];
__device__ float g_qrot[(size_t)B_*NH_*N_*HD_];
__device__ float g_krot[(size_t)B_*NH_*KV_*HD_];
__device__ float g_v   [(size_t)B_*NH_*KV_*HD_];
__device__ float g_stats[2*DM_];

// split-bf16 weight storage ([N,K] layout, hi+lo)
#define WTOT 13565952
#define OFF_QKV   0
#define OFF_OUT   1769472
#define OFF_FF1W1 2359296
#define OFF_FF1W2 4718592
#define OFF_PW1   7077888
#define OFF_PW2   8257536
#define OFF_FF2W1 8847360
#define OFF_FF2W2 11206656
__device__ __nv_bfloat16 g_whi[WTOT];
__device__ __nv_bfloat16 g_wlo[WTOT];
// split-bf16 activation scratch ([M,K]; max 4096*3072)
__device__ __nv_bfloat16 g_ahi[12582912];
__device__ __nv_bfloat16 g_alo[12582912];

// ---------------- FMA-only transcendentals ----------------------------------
__device__ __forceinline__ float fexp(float x) {
    x = fmaxf(x, -87.0f);
    float z = x * 1.44269504088896340f;
    float r = z + 12582912.0f;
    int   n = __float_as_int(r) - 0x4B400000;
    float f = z - (r - 12582912.0f);
    float p = 1.5403530393e-4f;
    p = fmaf(p, f, 1.3333558146e-3f);
    p = fmaf(p, f, 9.6181291076e-3f);
    p = fmaf(p, f, 5.5504108664e-2f);
    p = fmaf(p, f, 2.4022650696e-1f);
    p = fmaf(p, f, 6.9314718056e-1f);
    p = fmaf(p, f, 1.0f);
    return __int_as_float((n + 127) << 23) * p;
}
__device__ __forceinline__ float fsig(float z) {
    float e = fexp(-fabsf(z));
    float d = 1.0f + e;                          // [1,2]
    float r = fmaf(-0.457107f, d, 1.457107f);    // seed valid on [1,2]
    r = r * fmaf(-d, r, 2.0f);
    r = r * fmaf(-d, r, 2.0f);
    r = r * fmaf(-d, r, 2.0f);
    return (z >= 0.0f) ? r : e * r;
}
__device__ __forceinline__ float fgelu(float x) {
    float u = 1.5957691216057308f * fmaf(0.044715f * x, x * x, x);
    return x * fsig(u);
}

// ---------------- rmsnorm ----------------------------------------------------
__global__ __launch_bounds__(256) void rmsnorm_kernel(
    const float* __restrict__ x, const float* __restrict__ w,
    float* __restrict__ out)
{
    int row = blockIdx.x;
    const float* xr = x + (size_t)row * DM_;
    float v[3]; float s = 0.f;
#pragma unroll
    for (int i = 0; i < 3; i++) {
        v[i] = xr[threadIdx.x + i * 256];
        s = fmaf(v[i], v[i], s);
    }
#pragma unroll
    for (int off = 16; off; off >>= 1) s += __shfl_xor_sync(~0u, s, off);
    __shared__ float red[8];
    if ((threadIdx.x & 31) == 0) red[threadIdx.x >> 5] = s;
    __syncthreads();
    float tot = 0.f;
#pragma unroll
    for (int i = 0; i < 8; i++) tot += red[i];
    float scale = rsqrtf(tot * (1.0f / DM_) + EPSF);
    float* orow = out + (size_t)row * DM_;
#pragma unroll
    for (int i = 0; i < 3; i++) {
        int c = threadIdx.x + i * 256;
        orow[c] = v[i] * scale * w[c];
    }
}

// ---------------- split-bf16 conversion kernels ------------------------------
__global__ __launch_bounds__(256) void convA_k(
    const float* __restrict__ A, __nv_bfloat16* __restrict__ hi,
    __nv_bfloat16* __restrict__ lo, int total)
{
    int i = blockIdx.x * 256 + threadIdx.x;
    if (i < total) {
        float x = A[i];
        __nv_bfloat16 h = __float2bfloat16(x);
        hi[i] = h;
        lo[i] = __float2bfloat16(x - __bfloat162float(h));
    }
}

// W [K,N] row-major -> hi/lo bf16 [N,K] (transposed), 32x32 smem tiles
__global__ __launch_bounds__(1024) void convW_k(
    const float* __restrict__ W, __nv_bfloat16* __restrict__ hi,
    __nv_bfloat16* __restrict__ lo, int K, int N)
{
    __shared__ float t[32][33];
    int n0 = blockIdx.x * 32, k0 = blockIdx.y * 32;
    int tx = threadIdx.x, ty = threadIdx.y;
    t[ty][tx] = W[(size_t)(k0 + ty) * N + n0 + tx];
    __syncthreads();
    float x = t[tx][ty];                       // = W[k0+tx][n0+ty]
    __nv_bfloat16 h = __float2bfloat16(x);
    size_t o = (size_t)(n0 + ty) * K + k0 + tx;
    hi[o] = h;
    lo[o] = __float2bfloat16(x - __bfloat162float(h));
}

// ---------------- mma.sync split-bf16 GEMM -----------------------------------
// C[M,N] = A[M,K] @ W[K,N], with B = W^T as [N,K] hi/lo bf16.
// CTA 128x128, 8 warps (warp tile 32x64), K chunks of 64.
// smem tiles: 128 rows x 72 bf16 (64 used + 8 pad) -> 144B stride = 36 banks:
// fragment lds.b32 bank = (4*row + tig) mod 32 -> conflict-free.
enum { EPI_NONE = 0, EPI_BIAS, EPI_GELU, EPI_HALF_RES, EPI_RES };

#define TILE_B   18432                  // 128*72*2
#define MMG_SMEM (4*TILE_B)             // 73728

__device__ __forceinline__ uint32_t lds2(const char* base, int row, int col) {
    return *(const uint32_t*)(base + row * 144 + col * 2);
}
__device__ __forceinline__ void mma16816(float* c, const uint32_t* a,
                                         const uint32_t* b) {
    asm volatile(
        "mma.sync.aligned.m16n8k16.row.col.f32.bf16.bf16.f32 "
        "{%0,%1,%2,%3}, {%4,%5,%6,%7}, {%8,%9}, {%0,%1,%2,%3};"
        : "+f"(c[0]), "+f"(c[1]), "+f"(c[2]), "+f"(c[3])
        : "r"(a[0]), "r"(a[1]), "r"(a[2]), "r"(a[3]), "r"(b[0]), "r"(b[1]));
}

template <int EPI>
__global__ __launch_bounds__(256, 2) void mmagemm_k(
    const __nv_bfloat16* __restrict__ Ahi, const __nv_bfloat16* __restrict__ Alo,
    const __nv_bfloat16* __restrict__ Bhi, const __nv_bfloat16* __restrict__ Blo,
    const float* __restrict__ bias, const float* __restrict__ res,
    float* __restrict__ C, int M, int N, int K)
{
    extern __shared__ char smem[];
    char* sAh = smem;
    char* sAl = smem + TILE_B;
    char* sBh = smem + 2 * TILE_B;
    char* sBl = smem + 3 * TILE_B;

    const int tid = threadIdx.x, wid = tid >> 5, lane = tid & 31;
    const int g = lane >> 2, t = lane & 3;
    const int wm = (wid & 3) * 32, wn = (wid >> 2) * 64;
    const int cRow = blockIdx.y * 128, cCol = blockIdx.x * 128;

    float acc[2][8][4] = {};

    const int nchunks = K >> 6;
    for (int c = 0; c < nchunks; c++) {
        __syncthreads();
#pragma unroll
        for (int it = 0; it < 16; it++) {
            int e = tid + it * 256;            // 4096 x 16B segments
            int tile = e >> 10;
            int r = (e >> 3) & 127;
            int gs = e & 7;
            const __nv_bfloat16* src;
            char* dst;
            if (tile == 0)      { src = Ahi + (size_t)(cRow + r) * K + c * 64 + gs * 8; dst = sAh; }
            else if (tile == 1) { src = Alo + (size_t)(cRow + r) * K + c * 64 + gs * 8; dst = sAl; }
            else if (tile == 2) { src = Bhi + (size_t)(cCol + r) * K + c * 64 + gs * 8; dst = sBh; }
            else                { src = Blo + (size_t)(cCol + r) * K + c * 64 + gs * 8; dst = sBl; }
            *(uint4*)(dst + r * 144 + gs * 16) = *(const uint4*)src;
        }
        __syncthreads();

#pragma unroll
        for (int ks = 0; ks < 4; ks++) {
            const int k0 = ks * 16;
            uint32_t af[2][4], bfr[8][2];
            // ---- term 1: Ahi * Bhi
#pragma unroll
            for (int i = 0; i < 2; i++) {
                int br = wm + i * 16 + g;
                af[i][0] = lds2(sAh, br,     k0 + t * 2);
                af[i][1] = lds2(sAh, br + 8, k0 + t * 2);
                af[i][2] = lds2(sAh, br,     k0 + t * 2 + 8);
                af[i][3] = lds2(sAh, br + 8, k0 + t * 2 + 8);
            }
#pragma unroll
            for (int j = 0; j < 8; j++) {
                int bn = wn + j * 8 + g;
                bfr[j][0] = lds2(sBh, bn, k0 + t * 2);
                bfr[j][1] = lds2(sBh, bn, k0 + t * 2 + 8);
            }
#pragma unroll
            for (int i = 0; i < 2; i++)
#pragma unroll
                for (int j = 0; j < 8; j++)
                    mma16816(acc[i][j], af[i], bfr[j]);
            // ---- term 2: Ahi * Blo
#pragma unroll
            for (int j = 0; j < 8; j++) {
                int bn = wn + j * 8 + g;
                bfr[j][0] = lds2(sBl, bn, k0 + t * 2);
                bfr[j][1] = lds2(sBl, bn, k0 + t * 2 + 8);
            }
#pragma unroll
            for (int i = 0; i < 2; i++)
#pragma unroll
                for (int j = 0; j < 8; j++)
                    mma16816(acc[i][j], af[i], bfr[j]);
            // ---- term 3: Alo * Bhi
#pragma unroll
            for (int i = 0; i < 2; i++) {
                int br = wm + i * 16 + g;
                af[i][0] = lds2(sAl, br,     k0 + t * 2);
                af[i][1] = lds2(sAl, br + 8, k0 + t * 2);
                af[i][2] = lds2(sAl, br,     k0 + t * 2 + 8);
                af[i][3] = lds2(sAl, br + 8, k0 + t * 2 + 8);
            }
#pragma unroll
            for (int j = 0; j < 8; j++) {
                int bn = wn + j * 8 + g;
                bfr[j][0] = lds2(sBh, bn, k0 + t * 2);
                bfr[j][1] = lds2(sBh, bn, k0 + t * 2 + 8);
            }
#pragma unroll
            for (int i = 0; i < 2; i++)
#pragma unroll
                for (int j = 0; j < 8; j++)
                    mma16816(acc[i][j], af[i], bfr[j]);
        }
    }

    // ---- epilogue: c0,c1 at (row, cc..cc+1); c2,c3 at (row+8, cc..cc+1)
#pragma unroll
    for (int i = 0; i < 2; i++) {
        int r0 = cRow + wm + i * 16 + g;
#pragma unroll
        for (int j = 0; j < 8; j++) {
            int cc = cCol + wn + j * 8 + t * 2;
#pragma unroll
            for (int h = 0; h < 2; h++) {       // h=0 -> row r0, h=1 -> r0+8
                size_t r = (size_t)(r0 + h * 8);
                float o[2];
#pragma unroll
                for (int u = 0; u < 2; u++) {
                    float v = acc[i][j][h * 2 + u];
                    int ccc = cc + u;
                    if (EPI == EPI_BIAS)     v = v + bias[ccc];
                    if (EPI == EPI_GELU)     v = fgelu(v + bias[ccc]);
                    if (EPI == EPI_HALF_RES) v = fmaf(0.5f, v + bias[ccc], res[r * N + ccc]);
                    if (EPI == EPI_RES)      v = v + res[r * N + ccc];
                    o[u] = v;
                }
                *(float2*)&C[r * N + cc] = *(float2*)o;
            }
        }
    }
}

// ---------------- qkv post: per-head rmsnorm + rope + scatter ----------------
__global__ __launch_bounds__(384) void qkvpost_kernel(
    const float* __restrict__ qkv, const float* __restrict__ qw,
    const float* __restrict__ kw, float* __restrict__ kvout,
    float* __restrict__ qrot, float* __restrict__ krot,
    float* __restrict__ vout)
{
    int row = blockIdx.x;
    int b = row >> 11, n = row & 2047;
    int h = threadIdx.x >> 5, l = threadIdx.x & 31;
    const float* base = qkv + (size_t)row * (3 * NH_ * HD_) + h * (HD_ * 3);
    float q0 = base[l * 3 + 0],        k0 = base[l * 3 + 1],        v0 = base[l * 3 + 2];
    float q1 = base[(l + 32) * 3 + 0], k1 = base[(l + 32) * 3 + 1], v1 = base[(l + 32) * 3 + 2];
    float sq = fmaf(q0, q0, q1 * q1), sk = fmaf(k0, k0, k1 * k1);
#pragma unroll
    for (int off = 16; off; off >>= 1) {
        sq += __shfl_xor_sync(~0u, sq, off);
        sk += __shfl_xor_sync(~0u, sk, off);
    }
    float rq = rsqrtf(sq * (1.0f / HD_) + EPSF);
    float rk = rsqrtf(sk * (1.0f / HD_) + EPSF);
    q0 *= rq * qw[l];  q1 *= rq * qw[l + 32];
    k0 *= rk * kw[l];  k1 *= rk * kw[l + 32];

    int t = CACHE_ + n;
    size_t kvo = ((((size_t)b * KV_ + t) * 2 + 0) * NH_ + h) * HD_;
    kvout[kvo + l] = k0;  kvout[kvo + l + 32] = k1;
    kvout[kvo + NH_ * HD_ + l] = v0;  kvout[kvo + NH_ * HD_ + l + 32] = v1;

    float inv = expf(-(float)l * (9.210340371976184f / 32.0f));
    float ang = (float)t * inv;
    float sn, cs; sincosf(ang, &sn, &cs);
    size_t qidx = (((size_t)(b * NH_ + h)) * N_ + n) * HD_;
    qrot[qidx + l]      = (q0 * cs - q1 * sn) * 0.125f;
    qrot[qidx + l + 32] = (q1 * cs + q0 * sn) * 0.125f;
    size_t kidx = (((size_t)(b * NH_ + h)) * KV_ + t) * HD_;
    krot[kidx + l]      = k0 * cs - k1 * sn;
    krot[kidx + l + 32] = k1 * cs + k0 * sn;
    vout[kidx + l] = v0;  vout[kidx + l + 32] = v1;
}

// ---------------- cache prep -------------------------------------------------
__global__ __launch_bounds__(384) void cacheprep_kernel(
    const float* __restrict__ cached, float* __restrict__ kvout,
    float* __restrict__ krot, float* __restrict__ vout)
{
    int row = blockIdx.x;
    int b = row >> 9, t = row & 511;
    int h = threadIdx.x >> 5, l = threadIdx.x & 31;
    size_t ci = ((((size_t)b * CACHE_ + t) * 2 + 0) * NH_ + h) * HD_;
    float k0 = cached[ci + l],        k1 = cached[ci + l + 32];
    float v0 = cached[ci + NH_ * HD_ + l], v1 = cached[ci + NH_ * HD_ + l + 32];
    size_t kvo = ((((size_t)b * KV_ + t) * 2 + 0) * NH_ + h) * HD_;
    kvout[kvo + l] = k0;  kvout[kvo + l + 32] = k1;
    kvout[kvo + NH_ * HD_ + l] = v0;  kvout[kvo + NH_ * HD_ + l + 32] = v1;
    float inv = expf(-(float)l * (9.210340371976184f / 32.0f));
    float ang = (float)t * inv;
    float sn, cs; sincosf(ang, &sn, &cs);
    size_t kidx = (((size_t)(b * NH_ + h)) * KV_ + t) * HD_;
    krot[kidx + l]      = k0 * cs - k1 * sn;
    krot[kidx + l + 32] = k1 * cs + k0 * sn;
    vout[kidx + l] = v0;  vout[kidx + l + 32] = v1;
}

// ---------------- flash attention (fp32) -------------------------------------
__global__ __launch_bounds__(256) void flash_kernel(
    const float* __restrict__ Q, const float* __restrict__ Kr,
    const float* __restrict__ V, float* __restrict__ O)
{
    extern __shared__ float sm[];
    float* Qst = sm;
    float* Kst = sm + 4096;
    float* Vs  = sm + 8192;
    float* Ssm = sm + 12288;
    __shared__ float m_s[64], l_s[64], c_s[64];

    int tid = threadIdx.x;
    int qt = blockIdx.x, h = blockIdx.y, b = blockIdx.z;
    const float* qbase = Q + (((size_t)(b * NH_ + h)) * N_ + qt * 64) * HD_;
    const float* kbase = Kr + ((size_t)(b * NH_ + h)) * KV_ * HD_;
    const float* vbase = V  + ((size_t)(b * NH_ + h)) * KV_ * HD_;

#pragma unroll
    for (int it = 0; it < 4; it++) {
        int e = tid + it * 256;
        int q = e >> 4, d4 = (e & 15) * 4;
        float4 a = *(const float4*)(qbase + q * 64 + d4);
        Qst[(d4 + 0) * 64 + q] = a.x; Qst[(d4 + 1) * 64 + q] = a.y;
        Qst[(d4 + 2) * 64 + q] = a.z; Qst[(d4 + 3) * 64 + q] = a.w;
    }
    if (tid < 64) { m_s[tid] = -1e30f; l_s[tid] = 0.f; }
    int ty = tid >> 4, tx = tid & 15;
    float o[4][4] = {};

    for (int kc = 0; kc < KV_ / 64; kc++) {
        const float* kb = kbase + (size_t)kc * 64 * 64;
        const float* vb = vbase + (size_t)kc * 64 * 64;
        __syncthreads();
#pragma unroll
        for (int it = 0; it < 4; it++) {
            int e = tid + it * 256;
            int r = e >> 4, d4 = (e & 15) * 4;
            float4 a = *(const float4*)(kb + r * 64 + d4);
            Kst[(d4 + 0) * 64 + r] = a.x; Kst[(d4 + 1) * 64 + r] = a.y;
            Kst[(d4 + 2) * 64 + r] = a.z; Kst[(d4 + 3) * 64 + r] = a.w;
            *(float4*)&Vs[r * 64 + d4] = *(const float4*)(vb + r * 64 + d4);
        }
        __syncthreads();
        float s[4][4] = {};
#pragma unroll 16
        for (int d = 0; d < 64; d++) {
            float4 qa = *(float4*)&Qst[d * 64 + ty * 4];
            float4 ka = *(float4*)&Kst[d * 64 + tx * 4];
            float ra[4] = {qa.x, qa.y, qa.z, qa.w};
            float rb[4] = {ka.x, ka.y, ka.z, ka.w};
#pragma unroll
            for (int i = 0; i < 4; i++)
#pragma unroll
                for (int j = 0; j < 4; j++)
                    s[i][j] = fmaf(ra[i], rb[j], s[i][j]);
        }
#pragma unroll
        for (int i = 0; i < 4; i++)
            *(float4*)&Ssm[(ty * 4 + i) * 68 + tx * 4] = *(float4*)s[i];
        __syncthreads();
        if (tid < 64) {
            float mo = m_s[tid], mx = mo;
            const float* srow = &Ssm[tid * 68];
#pragma unroll 16
            for (int kk = 0; kk < 64; kk++) mx = fmaxf(mx, srow[kk]);
            float corr = fexp(mo - mx);
            float l = l_s[tid] * corr;
            float* prow = &Ssm[tid * 68];
#pragma unroll 8
            for (int kk = 0; kk < 64; kk++) {
                float p = fexp(prow[kk] - mx);
                prow[kk] = p;
                l += p;
            }
            m_s[tid] = mx; l_s[tid] = l; c_s[tid] = corr;
        }
        __syncthreads();
#pragma unroll
        for (int i = 0; i < 4; i++) {
            float cc = c_s[ty * 4 + i];
#pragma unroll
            for (int j = 0; j < 4; j++) o[i][j] *= cc;
        }
#pragma unroll 8
        for (int kk = 0; kk < 64; kk++) {
            float4 vv = *(float4*)&Vs[kk * 64 + tx * 4];
            float rv[4] = {vv.x, vv.y, vv.z, vv.w};
#pragma unroll
            for (int i = 0; i < 4; i++) {
                float p = Ssm[(ty * 4 + i) * 68 + kk];
#pragma unroll
                for (int j = 0; j < 4; j++)
                    o[i][j] = fmaf(p, rv[j], o[i][j]);
            }
        }
    }
    __syncthreads();
#pragma unroll
    for (int i = 0; i < 4; i++) {
        int q = ty * 4 + i;
        float invl = 1.0f / l_s[q];
        size_t row = (size_t)b * N_ + qt * 64 + q;
        float r4[4];
#pragma unroll
        for (int j = 0; j < 4; j++) r4[j] = o[i][j] * invl;
        *(float4*)&O[row * DM_ + h * HD_ + tx * 4] = *(float4*)r4;
    }
}

// ---------------- conv module pieces -----------------------------------------
__global__ __launch_bounds__(256) void glu_kernel(
    const float* __restrict__ in, float* __restrict__ out)
{
    int idx = blockIdx.x * 256 + threadIdx.x;
    int r = idx / DM_, c = idx - r * DM_;
    float a  = in[(size_t)r * (2 * DM_) + c];
    float bb = in[(size_t)r * (2 * DM_) + DM_ + c];
    out[idx] = a * fsig(bb);
}

__global__ void zero_stats_kernel(float* __restrict__ st) {
    st[blockIdx.x * 256 + threadIdx.x] = 0.f;
}

__global__ __launch_bounds__(768) void dwconv_kernel(
    const float* __restrict__ in, const float* __restrict__ w,
    const float* __restrict__ bias, float* __restrict__ out)
{
    int row = blockIdx.x;
    int b = row >> 11, t = row & 2047;
    int c = threadIdx.x;
    const float* basep = in + ((size_t)b * N_) * DM_ + c;
    const float* wp = w + c * 31;
    float acc = bias[c];
#pragma unroll
    for (int k = 0; k < 31; k++) {
        int tt = t + k - 15;
        if (tt >= 0 && tt < N_)
            acc = fmaf(basep[(size_t)tt * DM_], wp[k], acc);
    }
    out[(size_t)row * DM_ + c] = acc;
}

__global__ __launch_bounds__(256) void stats_kernel(
    const float* __restrict__ x, float* __restrict__ st)
{
    int blk = blockIdx.x, tid = threadIdx.x;
    float s[3] = {}, ss[3] = {};
    for (int r = 0; r < 64; r++) {
        size_t row = (size_t)blk * 64 + r;
#pragma unroll
        for (int i = 0; i < 3; i++) {
            float v = x[row * DM_ + tid + i * 256];
            s[i] += v;
            ss[i] = fmaf(v, v, ss[i]);
        }
    }
#pragma unroll
    for (int i = 0; i < 3; i++) {
        atomicAdd(&st[tid + i * 256], s[i]);
        atomicAdd(&st[DM_ + tid + i * 256], ss[i]);
    }
}

__global__ __launch_bounds__(256) void bnswish_kernel(
    float* __restrict__ x, const float* __restrict__ st,
    const float* __restrict__ g, const float* __restrict__ bt)
{
    int idx = blockIdx.x * 256 + threadIdx.x;
    int c = idx % DM_;
    float m   = st[c] * (1.0f / ROWS_);
    float var = st[DM_ + c] * (1.0f / ROWS_) - m * m;
    float y = (x[idx] - m) * rsqrtf(var + EPSF) * g[c] + bt[c];
    x[idx] = y * fsig(y);
}

// ---------------- host -------------------------------------------------------
static float* symaddr(const void* s) {
    void* p = nullptr;
    cudaGetSymbolAddress(&p, s);
    return (float*)p;
}
static __nv_bfloat16* symaddr_bf(const void* s) {
    void* p = nullptr;
    cudaGetSymbolAddress(&p, s);
    return (__nv_bfloat16*)p;
}

template <int EPI>
static void run_gemm(const float* A, __nv_bfloat16* whi, __nv_bfloat16* wlo,
                     const float* bias, const float* res, float* C,
                     int M, int N, int K,
                     __nv_bfloat16* ahi, __nv_bfloat16* alo)
{
    int total = M * K;
    convA_k<<<(total + 255) / 256, 256>>>(A, ahi, alo, total);
    mmagemm_k<EPI><<<dim3(N / 128, M / 128), 256, MMG_SMEM>>>(
        ahi, alo, whi, wlo, bias, res, C, M, N, K);
}

extern "C" void kernel_launch(void* const* d_in, const int* in_sizes, int n_in,
                              void* d_out, int out_size)
{
    const float* x = (const float*)d_in[0];
    int ic = 4;
    for (int i = 1; i < n_in; i++)
        if (in_sizes[i] == B_ * KV_ * 2 * NH_ * HD_) { ic = i; break; }
    const float* cached  = (const float*)d_in[ic];
    const float* ff1_nw  = (const float*)d_in[ic + 1];
    const float* ff1_w1  = (const float*)d_in[ic + 2];
    const float* ff1_b1  = (const float*)d_in[ic + 3];
    const float* ff1_w2  = (const float*)d_in[ic + 4];
    const float* ff1_b2  = (const float*)d_in[ic + 5];
    const float* attn_nw = (const float*)d_in[ic + 6];
    const float* qkv_w   = (const float*)d_in[ic + 7];
    const float* out_w   = (const float*)d_in[ic + 8];
    const float* q_nw    = (const float*)d_in[ic + 9];
    const float* k_nw    = (const float*)d_in[ic + 10];
    const float* conv_nw = (const float*)d_in[ic + 11];
    const float* pw1_w   = (const float*)d_in[ic + 12];
    const float* pw1_b   = (const float*)d_in[ic + 13];
    const float* dw_w    = (const float*)d_in[ic + 14];
    const float* dw_b    = (const float*)d_in[ic + 15];
    const float* bn_g    = (const float*)d_in[ic + 16];
    const float* bn_b    = (const float*)d_in[ic + 17];
    const float* pw2_w   = (const float*)d_in[ic + 18];
    const float* pw2_b   = (const float*)d_in[ic + 19];
    const float* ff2_nw  = (const float*)d_in[ic + 20];
    const float* ff2_w1  = (const float*)d_in[ic + 21];
    const float* ff2_b1  = (const float*)d_in[ic + 22];
    const float* ff2_w2  = (const float*)d_in[ic + 23];
    const float* ff2_b2  = (const float*)d_in[ic + 24];
    const float* out_nw  = (const float*)d_in[ic + 25];

    float* outx = (float*)d_out;
    bool write_kv = (out_size >= ROWS_ * DM_ + B_ * KV_ * 2 * NH_ * HD_);
    float* kvdst = write_kv ? (outx + (size_t)ROWS_ * DM_) : symaddr(g_kv);

    float* p_y    = symaddr(g_y);
    float* p_h    = symaddr(g_h);
    float* p_x1   = symaddr(g_x1);
    float* p_x2   = symaddr(g_x2);
    float* p_attn = symaddr(g_attn);
    float* p_glu  = symaddr(g_glu);
    float* p_conv = symaddr(g_conv);
    float* p_xc   = symaddr(g_xc);
    float* p_x3   = symaddr(g_x3);
    float* p_qr   = symaddr(g_qrot);
    float* p_kr   = symaddr(g_krot);
    float* p_v    = symaddr(g_v);
    float* p_st   = symaddr(g_stats);
    __nv_bfloat16* whi = symaddr_bf(g_whi);
    __nv_bfloat16* wlo = symaddr_bf(g_wlo);
    __nv_bfloat16* ahi = symaddr_bf(g_ahi);
    __nv_bfloat16* alo = symaddr_bf(g_alo);

    const int FLASH_SMEM = (4096 * 3 + 64 * 68) * 4;   // 66560
    cudaFuncSetAttribute(flash_kernel,
                         cudaFuncAttributeMaxDynamicSharedMemorySize, FLASH_SMEM);
    cudaFuncSetAttribute(mmagemm_k<EPI_NONE>,
                         cudaFuncAttributeMaxDynamicSharedMemorySize, MMG_SMEM);
    cudaFuncSetAttribute(mmagemm_k<EPI_BIAS>,
                         cudaFuncAttributeMaxDynamicSharedMemorySize, MMG_SMEM);
    cudaFuncSetAttribute(mmagemm_k<EPI_GELU>,
                         cudaFuncAttributeMaxDynamicSharedMemorySize, MMG_SMEM);
    cudaFuncSetAttribute(mmagemm_k<EPI_HALF_RES>,
                         cudaFuncAttributeMaxDynamicSharedMemorySize, MMG_SMEM);
    cudaFuncSetAttribute(mmagemm_k<EPI_RES>,
                         cudaFuncAttributeMaxDynamicSharedMemorySize, MMG_SMEM);

    // ---- weight conversions (weights -> [N,K] hi/lo bf16) ------------------
    dim3 cb(32, 32);
    convW_k<<<dim3(2304/32,  768/32), cb>>>(qkv_w,  whi+OFF_QKV,   wlo+OFF_QKV,    768, 2304);
    convW_k<<<dim3( 768/32,  768/32), cb>>>(out_w,  whi+OFF_OUT,   wlo+OFF_OUT,    768,  768);
    convW_k<<<dim3(3072/32,  768/32), cb>>>(ff1_w1, whi+OFF_FF1W1, wlo+OFF_FF1W1,  768, 3072);
    convW_k<<<dim3( 768/32, 3072/32), cb>>>(ff1_w2, whi+OFF_FF1W2, wlo+OFF_FF1W2, 3072,  768);
    convW_k<<<dim3(1536/32,  768/32), cb>>>(pw1_w,  whi+OFF_PW1,   wlo+OFF_PW1,    768, 1536);
    convW_k<<<dim3( 768/32,  768/32), cb>>>(pw2_w,  whi+OFF_PW2,   wlo+OFF_PW2,    768,  768);
    convW_k<<<dim3(3072/32,  768/32), cb>>>(ff2_w1, whi+OFF_FF2W1, wlo+OFF_FF2W1,  768, 3072);
    convW_k<<<dim3( 768/32, 3072/32), cb>>>(ff2_w2, whi+OFF_FF2W2, wlo+OFF_FF2W2, 3072,  768);

    // ---- FF1: x1 = 0.5*(gelu(rms(x)W1+b1)W2 + b2) + x
    rmsnorm_kernel<<<ROWS_, 256>>>(x, ff1_nw, p_y);
    run_gemm<EPI_GELU>(p_y, whi+OFF_FF1W1, wlo+OFF_FF1W1, ff1_b1, nullptr,
                       p_h, ROWS_, FF_, DM_, ahi, alo);
    run_gemm<EPI_HALF_RES>(p_h, whi+OFF_FF1W2, wlo+OFF_FF1W2, ff1_b2, x,
                           p_x1, ROWS_, DM_, FF_, ahi, alo);

    // ---- Attention
    rmsnorm_kernel<<<ROWS_, 256>>>(p_x1, attn_nw, p_y);
    run_gemm<EPI_NONE>(p_y, whi+OFF_QKV, wlo+OFF_QKV, nullptr, nullptr,
                       p_h, ROWS_, 3 * NH_ * HD_, DM_, ahi, alo);
    cacheprep_kernel<<<B_ * CACHE_, 384>>>(cached, kvdst, p_kr, p_v);
    qkvpost_kernel<<<ROWS_, 384>>>(p_h, q_nw, k_nw, kvdst, p_qr, p_kr, p_v);
    flash_kernel<<<dim3(N_ / 64, NH_, B_), 256, FLASH_SMEM>>>(p_qr, p_kr, p_v, p_attn);
    run_gemm<EPI_RES>(p_attn, whi+OFF_OUT, wlo+OFF_OUT, nullptr, p_x1,
                      p_x2, ROWS_, DM_, DM_, ahi, alo);

    // ---- Conv module
    rmsnorm_kernel<<<ROWS_, 256>>>(p_x2, conv_nw, p_y);
    run_gemm<EPI_BIAS>(p_y, whi+OFF_PW1, wlo+OFF_PW1, pw1_b, nullptr,
                       p_h, ROWS_, 2 * DM_, DM_, ahi, alo);
    glu_kernel<<<(ROWS_ * DM_) / 256, 256>>>(p_h, p_glu);
    zero_stats_kernel<<<(2 * DM_) / 256, 256>>>(p_st);
    dwconv_kernel<<<ROWS_, DM_>>>(p_glu, dw_w, dw_b, p_conv);
    stats_kernel<<<64, 256>>>(p_conv, p_st);
    bnswish_kernel<<<(ROWS_ * DM_) / 256, 256>>>(p_conv, p_st, bn_g, bn_b);
    run_gemm<EPI_BIAS>(p_conv, whi+OFF_PW2, wlo+OFF_PW2, pw2_b, nullptr,
                       p_xc, ROWS_, DM_, DM_, ahi, alo);

    // ---- FF2
    rmsnorm_kernel<<<ROWS_, 256>>>(p_xc, ff2_nw, p_y);
    run_gemm<EPI_GELU>(p_y, whi+OFF_FF2W1, wlo+OFF_FF2W1, ff2_b1, nullptr,
                       p_h, ROWS_, FF_, DM_, ahi, alo);
    run_gemm<EPI_HALF_RES>(p_h, whi+OFF_FF2W2, wlo+OFF_FF2W2, ff2_b2, p_xc,
                           p_x3, ROWS_, DM_, FF_, ahi, alo);

    // ---- final rmsnorm -> output x
    rmsnorm_kernel<<<ROWS_, 256>>>(p_x3, out_nw, outx);
}